// round 14
// baseline (speedup 1.0000x reference)
#include <cuda_runtime.h>
#include <math.h>

#define SEQ   2048
#define BATCH 64
#define DIN   512
#define DH    512

typedef unsigned long long u64;

// ---------------- f32x2 packed helpers ----------------
__device__ __forceinline__ u64 dupf(float x) {
    u64 d; asm("mov.b64 %0, {%1, %1};" : "=l"(d) : "f"(x)); return d;
}
__device__ __forceinline__ u64 packf2(float lo, float hi) {
    u64 d; asm("mov.b64 %0, {%1, %2};" : "=l"(d) : "f"(lo), "f"(hi)); return d;
}
__device__ __forceinline__ void fma2(u64& acc, u64 a, u64 b) {
    asm("fma.rn.f32x2 %0, %1, %2, %0;" : "+l"(acc) : "l"(a), "l"(b));
}
__device__ __forceinline__ float2 unpack2(u64 v) {
    float lo, hi;
    asm("mov.b64 {%0, %1}, %2;" : "=f"(lo), "=f"(hi) : "l"(v));
    return make_float2(lo, hi);
}

// ---------------- release/acquire flag ops ----------------
__device__ __forceinline__ void st_release_gpu(unsigned* p, unsigned v) {
    asm volatile("st.global.release.gpu.u32 [%0], %1;" :: "l"(p), "r"(v) : "memory");
}
__device__ __forceinline__ unsigned ld_acquire_gpu(const unsigned* p) {
    unsigned v;
    asm volatile("ld.global.acquire.gpu.u32 %0, [%1];" : "=r"(v) : "l"(p) : "memory");
    return v;
}

// ---------------- XLA fast tanh: clamp 7.99881172180175781, passthrough ----------------
__device__ __forceinline__ float xla_tanh(float x) {
    const float kClamp = 7.99881172180175781f;
    float ax = fabsf(x);
    float xc = fminf(fmaxf(x, -kClamp), kClamp);
    float x2 = xc * xc;
    float p = __fmaf_rn(x2, -2.76076847742355e-16f, 2.00018790482477e-13f);
    p = __fmaf_rn(x2, p, -8.60467152213735e-11f);
    p = __fmaf_rn(x2, p, 5.12229709037114e-08f);
    p = __fmaf_rn(x2, p, 1.48572235717979e-05f);
    p = __fmaf_rn(x2, p, 6.37261928875436e-04f);
    p = __fmaf_rn(x2, p, 4.89352455891786e-03f);
    p = xc * p;
    float q = __fmaf_rn(x2, 1.19825839466702e-06f, 1.18534705686654e-04f);
    q = __fmaf_rn(x2, q, 2.26843463243900e-03f);
    q = __fmaf_rn(x2, q, 4.89352518554385e-03f);
    float r = __fdiv_rn(p, q);
    return (ax < 0.0004f) ? x : r;
}

// ---------------- global state ----------------
__device__ float g_ring[2][BATCH][DH];       // L2-hot double-buffered h
__device__ unsigned g_flag[8 * 16 * 32];     // per (bg,cg) step flags

// ---------------- Kernel 1: xi = x @ W_i2h^T + b_i2h (f32x2 packed) ----------------
#define BM 64
#define BN 64
#define BK 16

__global__ void __launch_bounds__(256) i2h_gemm_kernel(
    const float* __restrict__ A, const float* __restrict__ Bw,
    const float* __restrict__ bias, float* __restrict__ C)
{
    __shared__ float As[BK][BM + 4];
    __shared__ float Bs[BK][BN + 4];
    const int bm = blockIdx.x, bn = blockIdx.y, tid = threadIdx.x;
    const int tm = (tid / 16) * 4, tn = (tid % 16) * 4;
    const int lr = tid / 4, lk = (tid % 4) * 4;
    const float* Aptr = A + ((size_t)bm * BM + lr) * DIN + lk;
    const float* Bptr = Bw + ((size_t)bn * BN + lr) * DIN + lk;

    u64 acc2[4][2];
    #pragma unroll
    for (int i = 0; i < 4; i++) { acc2[i][0] = 0ull; acc2[i][1] = 0ull; }

    for (int k0 = 0; k0 < DIN; k0 += BK) {
        float4 av = *(const float4*)(Aptr + k0);
        float4 bv = *(const float4*)(Bptr + k0);
        As[lk + 0][lr] = av.x; As[lk + 1][lr] = av.y;
        As[lk + 2][lr] = av.z; As[lk + 3][lr] = av.w;
        Bs[lk + 0][lr] = bv.x; Bs[lk + 1][lr] = bv.y;
        Bs[lk + 2][lr] = bv.z; Bs[lk + 3][lr] = bv.w;
        __syncthreads();
        #pragma unroll
        for (int k = 0; k < BK; k++) {
            float4 a4 = *(const float4*)&As[k][tm];
            u64 b01 = *(const u64*)&Bs[k][tn];
            u64 b23 = *(const u64*)&Bs[k][tn + 2];
            float am[4] = {a4.x, a4.y, a4.z, a4.w};
            #pragma unroll
            for (int i = 0; i < 4; i++) {
                u64 ad = dupf(am[i]);
                fma2(acc2[i][0], ad, b01);
                fma2(acc2[i][1], ad, b23);
            }
        }
        __syncthreads();
    }

    const float b0 = bias[bn * BN + tn + 0];
    const float b1 = bias[bn * BN + tn + 1];
    const float b2 = bias[bn * BN + tn + 2];
    const float b3 = bias[bn * BN + tn + 3];
    #pragma unroll
    for (int i = 0; i < 4; i++) {
        float2 p0 = unpack2(acc2[i][0]);
        float2 p1 = unpack2(acc2[i][1]);
        float4 o;
        o.x = p0.x + b0;
        o.y = p0.y + b1;
        o.z = p1.x + b2;
        o.w = p1.y + b3;
        *(float4*)&C[((size_t)bm * BM + tm + i) * DH + bn * BN + tn] = o;
    }
}

// ---------------- Kernel 2: persistent scan (f32x2 row-pair chains) ----------------
// 128 CTAs = bg(8 x 8 rows) x cg(16 x 32 cols). 128 threads = 4 warps.
// Thread: col = c0 + lane; warp w owns rows {2w, 2w+1}, both packed into the
// (lo,hi) lanes of ONE fma.rn.f32x2 chain. W pre-duplicated (w,w) in smem;
// h staged per-warp interleaved (hA[k],hB[k]) -> warp-uniform LDS broadcast.
// Per output element: identical ascending-k scalar chain -> (xi+dot)+b -> tanh.
#define WDST 514   // W dup stride in u64 (= 257 float4, odd -> conflict-free)
#define HWST 514   // per-warp h stride in u64
#define SMEM_BYTES ((32 * WDST + 4 * HWST) * 8)   // 131584 + 16448 = 148032

__global__ void __launch_bounds__(128, 1) rnn_scan_kernel(
    const float* __restrict__ h0, const float* __restrict__ W_h2h,
    const float* __restrict__ b_h2h, float* __restrict__ out,
    float* __restrict__ h_last)
{
    extern __shared__ u64 smu[];
    u64* Wdup = smu;                        // [32][WDST]
    u64* hw   = smu + 32 * WDST + (threadIdx.x >> 5) * HWST;  // this warp's h

    const int cg = blockIdx.x & 15;
    const int bg = blockIdx.x >> 4;
    const int c0 = cg * 32;
    const int b0 = bg * 8;
    const int tid = threadIdx.x;
    const int lane = tid & 31;
    const int w = tid >> 5;
    const int rA = 2 * w, rB = 2 * w + 1;
    const int col = c0 + lane;

    // stage W duplicated once: Wdup[cc][k] = (W[c0+cc][k], W[c0+cc][k])
    for (int idx = tid; idx < 32 * 512; idx += 128) {
        int cc = idx >> 9, k = idx & 511;
        Wdup[cc * WDST + k] = dupf(W_h2h[(size_t)(c0 + cc) * DH + k]);
    }

    const float bias = b_h2h[col];
    const ulonglong2* W2 = (const ulonglong2*)(Wdup + (size_t)lane * WDST);
    const ulonglong2* H2 = (const ulonglong2*)hw;

    const size_t oA = ((size_t)b0 + rA) * DH + col;   // + t*BATCH*DH
    const size_t oB = ((size_t)b0 + rB) * DH + col;
    unsigned* myflag  = &g_flag[(bg * 16 + cg) * 32];
    unsigned* pollflag = &g_flag[(bg * 16 + (lane & 15)) * 32];

    // prefetch xi(0)
    float xiA = out[oA];
    float xiB = out[oB];
    __syncthreads();

    for (int t = 0; t < SEQ; t++) {
        // ---- per-warp staging of rows rA,rB, interleaved (hA[k],hB[k]) ----
        const float4* sA = (t == 0)
            ? (const float4*)(h0 + (size_t)(b0 + rA) * DH)
            : (const float4*)(g_ring[1 ^ (t & 1)][b0 + rA]);
        const float4* sB = (t == 0)
            ? (const float4*)(h0 + (size_t)(b0 + rB) * DH)
            : (const float4*)(g_ring[1 ^ (t & 1)][b0 + rB]);
        #pragma unroll
        for (int j = 0; j < 4; j++) {
            int k4 = lane + 32 * j;               // float4 index (4 k per)
            float4 a = (t == 0) ? sA[k4] : __ldcg(sA + k4);
            float4 b = (t == 0) ? sB[k4] : __ldcg(sB + k4);
            ulonglong2 p01, p23;
            p01.x = packf2(a.x, b.x); p01.y = packf2(a.y, b.y);
            p23.x = packf2(a.z, b.z); p23.y = packf2(a.w, b.w);
            ((ulonglong2*)hw)[2 * k4]     = p01;
            ((ulonglong2*)hw)[2 * k4 + 1] = p23;
        }
        __syncwarp();

        // ---- ONE f32x2 chain = two ascending-k scalar chains (rows rA,rB) ----
        u64 acc = 0ull;
        #pragma unroll 16
        for (int k2 = 0; k2 < 256; k2++) {
            ulonglong2 wv = W2[k2];   // ((w2k,w2k), (w2k+1,w2k+1))
            ulonglong2 hv = H2[k2];   // ((hA2k,hB2k), (hA2k+1,hB2k+1))
            fma2(acc, hv.x, wv.x);
            fma2(acc, hv.y, wv.y);
        }
        float2 d = unpack2(acc);
        float vA = xla_tanh((xiA + d.x) + bias);
        float vB = xla_tanh((xiB + d.y) + bias);

        if (t == SEQ - 1) {
            out[(size_t)t * BATCH * DH + oA] = vA;
            out[(size_t)t * BATCH * DH + oB] = vB;
            if (h_last) { h_last[oA] = vA; h_last[oB] = vB; }
            __syncthreads();
            if (tid == 0) *myflag = 0u;   // replay-clean (launch boundary fences)
        } else {
            // h(t) into the hot ring (the only stores the release must order)
            g_ring[t & 1][b0 + rA][col] = vA;
            g_ring[t & 1][b0 + rB][col] = vB;
            __syncthreads();
            if (tid == 0) st_release_gpu(myflag, (unsigned)(t + 1));
            // fire-and-forget DRAM output + xi prefetch in the poll shadow
            out[(size_t)t * BATCH * DH + oA] = vA;
            out[(size_t)t * BATCH * DH + oB] = vB;
            xiA = out[(size_t)(t + 1) * BATCH * DH + oA];
            xiB = out[(size_t)(t + 1) * BATCH * DH + oB];
            // every warp polls independently (lanes 0..31 cover all 16 flags);
            // no post-poll __syncthreads -- warps proceed to their own staging
            while (ld_acquire_gpu(pollflag) < (unsigned)(t + 1)) { }
        }
    }
}

// ---------------- launch (single stream, graph-capture-safe) ----------------
extern "C" void kernel_launch(void* const* d_in, const int* in_sizes, int n_in,
                              void* d_out, int out_size) {
    const float* x     = (const float*)d_in[0];
    const float* h0    = (const float*)d_in[1];
    const float* W_i2h = (const float*)d_in[2];
    const float* b_i2h = (const float*)d_in[3];
    const float* W_h2h = (const float*)d_in[4];
    const float* b_h2h = (const float*)d_in[5];
    float* out = (float*)d_out;

    float* h_last = nullptr;
    if ((long long)out_size >= (long long)(SEQ + 1) * BATCH * DH)
        h_last = out + (size_t)SEQ * BATCH * DH;

    dim3 g1(SEQ * BATCH / BM, DH / BN);
    i2h_gemm_kernel<<<g1, 256>>>(x, W_i2h, b_i2h, out);

    cudaFuncSetAttribute(rnn_scan_kernel,
                         cudaFuncAttributeMaxDynamicSharedMemorySize, SMEM_BYTES);
    rnn_scan_kernel<<<128, 128, SMEM_BYTES>>>(h0, W_h2h, b_h2h, out, h_last);
}

// round 15
// speedup vs baseline: 1.1744x; 1.1744x over previous
#include <cuda_runtime.h>
#include <math.h>

#define SEQ   2048
#define BATCH 64
#define DIN   512
#define DH    512

typedef unsigned long long u64;

// ---------------- f32x2 packed helpers (GEMM only) ----------------
__device__ __forceinline__ u64 dupf(float x) {
    u64 d; asm("mov.b64 %0, {%1, %1};" : "=l"(d) : "f"(x)); return d;
}
__device__ __forceinline__ void fma2(u64& acc, u64 a, u64 b) {
    asm("fma.rn.f32x2 %0, %1, %2, %0;" : "+l"(acc) : "l"(a), "l"(b));
}
__device__ __forceinline__ float2 unpack2(u64 v) {
    float lo, hi;
    asm("mov.b64 {%0, %1}, %2;" : "=f"(lo), "=f"(hi) : "l"(v));
    return make_float2(lo, hi);
}

// ---------------- release/acquire flag ops ----------------
__device__ __forceinline__ void st_release_gpu(unsigned* p, unsigned v) {
    asm volatile("st.global.release.gpu.u32 [%0], %1;" :: "l"(p), "r"(v) : "memory");
}
__device__ __forceinline__ unsigned ld_acquire_gpu(const unsigned* p) {
    unsigned v;
    asm volatile("ld.global.acquire.gpu.u32 %0, [%1];" : "=r"(v) : "l"(p) : "memory");
    return v;
}

// ---------------- XLA fast tanh: clamp 7.99881172180175781, passthrough ----------------
__device__ __forceinline__ float xla_tanh(float x) {
    const float kClamp = 7.99881172180175781f;
    float ax = fabsf(x);
    float xc = fminf(fmaxf(x, -kClamp), kClamp);
    float x2 = xc * xc;
    float p = __fmaf_rn(x2, -2.76076847742355e-16f, 2.00018790482477e-13f);
    p = __fmaf_rn(x2, p, -8.60467152213735e-11f);
    p = __fmaf_rn(x2, p, 5.12229709037114e-08f);
    p = __fmaf_rn(x2, p, 1.48572235717979e-05f);
    p = __fmaf_rn(x2, p, 6.37261928875436e-04f);
    p = __fmaf_rn(x2, p, 4.89352455891786e-03f);
    p = xc * p;
    float q = __fmaf_rn(x2, 1.19825839466702e-06f, 1.18534705686654e-04f);
    q = __fmaf_rn(x2, q, 2.26843463243900e-03f);
    q = __fmaf_rn(x2, q, 4.89352518554385e-03f);
    float r = __fdiv_rn(p, q);
    return (ax < 0.0004f) ? x : r;
}

// ---------------- global state ----------------
__device__ float g_ring[2][BATCH][DH];       // L2-hot double-buffered h
__device__ unsigned g_flag[8 * 16 * 32];     // per (bg,cg) step flags

// ---------------- Kernel 1: xi = x @ W_i2h^T + b_i2h (f32x2 packed) ----------------
#define BM 64
#define BN 64
#define BK 16

__global__ void __launch_bounds__(256) i2h_gemm_kernel(
    const float* __restrict__ A, const float* __restrict__ Bw,
    const float* __restrict__ bias, float* __restrict__ C)
{
    __shared__ float As[BK][BM + 4];
    __shared__ float Bs[BK][BN + 4];
    const int bm = blockIdx.x, bn = blockIdx.y, tid = threadIdx.x;
    const int tm = (tid / 16) * 4, tn = (tid % 16) * 4;
    const int lr = tid / 4, lk = (tid % 4) * 4;
    const float* Aptr = A + ((size_t)bm * BM + lr) * DIN + lk;
    const float* Bptr = Bw + ((size_t)bn * BN + lr) * DIN + lk;

    u64 acc2[4][2];
    #pragma unroll
    for (int i = 0; i < 4; i++) { acc2[i][0] = 0ull; acc2[i][1] = 0ull; }

    for (int k0 = 0; k0 < DIN; k0 += BK) {
        float4 av = *(const float4*)(Aptr + k0);
        float4 bv = *(const float4*)(Bptr + k0);
        As[lk + 0][lr] = av.x; As[lk + 1][lr] = av.y;
        As[lk + 2][lr] = av.z; As[lk + 3][lr] = av.w;
        Bs[lk + 0][lr] = bv.x; Bs[lk + 1][lr] = bv.y;
        Bs[lk + 2][lr] = bv.z; Bs[lk + 3][lr] = bv.w;
        __syncthreads();
        #pragma unroll
        for (int k = 0; k < BK; k++) {
            float4 a4 = *(const float4*)&As[k][tm];
            u64 b01 = *(const u64*)&Bs[k][tn];
            u64 b23 = *(const u64*)&Bs[k][tn + 2];
            float am[4] = {a4.x, a4.y, a4.z, a4.w};
            #pragma unroll
            for (int i = 0; i < 4; i++) {
                u64 ad = dupf(am[i]);
                fma2(acc2[i][0], ad, b01);
                fma2(acc2[i][1], ad, b23);
            }
        }
        __syncthreads();
    }

    const float b0 = bias[bn * BN + tn + 0];
    const float b1 = bias[bn * BN + tn + 1];
    const float b2 = bias[bn * BN + tn + 2];
    const float b3 = bias[bn * BN + tn + 3];
    #pragma unroll
    for (int i = 0; i < 4; i++) {
        float2 p0 = unpack2(acc2[i][0]);
        float2 p1 = unpack2(acc2[i][1]);
        float4 o;
        o.x = p0.x + b0;
        o.y = p0.y + b1;
        o.z = p1.x + b2;
        o.w = p1.y + b3;
        *(float4*)&C[((size_t)bm * BM + tm + i) * DH + bn * BN + tn] = o;
    }
}

// ---------------- Kernel 2: persistent scan (quarter-pipelined sync) ----------------
// 128 CTAs = bg(8 x 8 rows) x cg(16 x 32 cols). 128 threads = 4 warps.
// Warp w: rows {2w, 2w+1}; lane = col. Chain consumes k ascending; cg-slice s
// lives at k in [32s,32s+32), so quarter q needs only flags 4q..4q+3. Every
// warp polls all 16 flags in ONE parallel acquire round + ballot; chains start
// after quarter 0 is ready; later quarters checked from the register mask.
#define WST 516    // W row stride (floats)
#define HST4 130   // h row stride (float4)

__global__ void __launch_bounds__(128, 1) rnn_scan_kernel(
    const float* __restrict__ h0, const float* __restrict__ W_h2h,
    const float* __restrict__ b_h2h, float* __restrict__ out,
    float* __restrict__ h_last)
{
    extern __shared__ float sm[];
    float* W_s = sm;                          // [32][WST]
    float4* h_s4 = (float4*)(sm + 32 * WST);  // [8][HST4]

    const int cg = blockIdx.x & 15;
    const int bg = blockIdx.x >> 4;
    const int c0 = cg * 32;
    const int b0 = bg * 8;
    const int tid = threadIdx.x;
    const int lane = tid & 31;
    const int w = tid >> 5;
    const int rA = 2 * w, rB = 2 * w + 1;
    const int col = c0 + lane;

    // stage W slice once
    for (int idx = tid; idx < 32 * 512; idx += 128) {
        int cc = idx >> 9, k = idx & 511;
        W_s[cc * WST + k] = W_h2h[(size_t)(c0 + cc) * DH + k];
    }
    const float bias = b_h2h[col];
    const float4* Wp  = (const float4*)&W_s[lane * WST];
    const float4* hA4 = h_s4 + rA * HST4;
    const float4* hB4 = h_s4 + rB * HST4;

    // staging: lanes 0-15 -> row rA, lanes 16-31 -> row rB; 8 float4 each
    const int srow = (lane < 16) ? rA : rB;
    const int sk = lane & 15;
    float4* sdst = h_s4 + srow * HST4;

    const size_t oA = ((size_t)b0 + rA) * DH + col;   // + t*BATCH*DH
    const size_t oB = ((size_t)b0 + rB) * DH + col;
    unsigned* myflag = &g_flag[(bg * 16 + cg) * 32];
    unsigned* watch  = &g_flag[(bg * 16 + (lane & 15)) * 32];

    float xiA = out[oA];
    float xiB = out[oB];
    __syncthreads();

    for (int t = 0; t < SEQ; t++) {
        const unsigned tgt = (unsigned)t;
        unsigned m = 0xFFFFFFFFu;
        if (t > 0) {
            unsigned v = (lane < 16) ? ld_acquire_gpu(watch) : 0u;
            m = __ballot_sync(0xFFFFFFFFu, (lane >= 16) || (v >= tgt));
        }
        #define WAITQ(q) \
            while (((m >> (4 * (q))) & 0xFu) != 0xFu) { \
                unsigned v_ = (lane < 16) ? ld_acquire_gpu(watch) : 0u; \
                m = __ballot_sync(0xFFFFFFFFu, (lane >= 16) || (v_ >= tgt)); \
            }

        const float4* src = (t == 0)
            ? (const float4*)(h0 + (size_t)(b0 + srow) * DH)
            : (const float4*)(g_ring[(t - 1) & 1][b0 + srow]);

        // pipelined: wait quarter, issue its LDG; STS+chain trail behind
        float4 q0a, q0b, q1a, q1b, q2a, q2b, q3a, q3b;
        WAITQ(0); q0a = __ldcg(src + sk);       q0b = __ldcg(src + sk + 16);
        WAITQ(1); q1a = __ldcg(src + sk + 32);  q1b = __ldcg(src + sk + 48);
        sdst[sk] = q0a; sdst[sk + 16] = q0b;
        WAITQ(2); q2a = __ldcg(src + sk + 64);  q2b = __ldcg(src + sk + 80);
        __syncwarp();

        float a0 = 0.f, a1 = 0.f;
        #define CHAIN(LO, HI) \
            _Pragma("unroll 8") \
            for (int k4 = (LO); k4 < (HI); k4++) { \
                float4 wv = Wp[k4]; \
                float4 ha = hA4[k4]; \
                float4 hb = hB4[k4]; \
                a0 = __fmaf_rn(ha.x, wv.x, a0); \
                a0 = __fmaf_rn(ha.y, wv.y, a0); \
                a0 = __fmaf_rn(ha.z, wv.z, a0); \
                a0 = __fmaf_rn(ha.w, wv.w, a0); \
                a1 = __fmaf_rn(hb.x, wv.x, a1); \
                a1 = __fmaf_rn(hb.y, wv.y, a1); \
                a1 = __fmaf_rn(hb.z, wv.z, a1); \
                a1 = __fmaf_rn(hb.w, wv.w, a1); \
            }

        CHAIN(0, 32)
        sdst[sk + 32] = q1a; sdst[sk + 48] = q1b;
        WAITQ(3); q3a = __ldcg(src + sk + 96);  q3b = __ldcg(src + sk + 112);
        __syncwarp();
        CHAIN(32, 64)
        sdst[sk + 64] = q2a; sdst[sk + 80] = q2b;
        __syncwarp();
        CHAIN(64, 96)
        sdst[sk + 96] = q3a; sdst[sk + 112] = q3b;
        __syncwarp();
        CHAIN(96, 128)
        #undef CHAIN
        #undef WAITQ

        float vA = xla_tanh((xiA + a0) + bias);
        float vB = xla_tanh((xiB + a1) + bias);

        if (t == SEQ - 1) {
            out[(size_t)t * BATCH * DH + oA] = vA;
            out[(size_t)t * BATCH * DH + oB] = vB;
            if (h_last) { h_last[oA] = vA; h_last[oB] = vB; }
            __syncthreads();
            if (tid == 0) *myflag = 0u;   // replay-clean (launch boundary fences)
        } else {
            // ring stores are the only ones the release must order
            g_ring[t & 1][b0 + rA][col] = vA;
            g_ring[t & 1][b0 + rB][col] = vB;
            __syncthreads();
            if (tid == 0) st_release_gpu(myflag, (unsigned)(t + 1));
            // fire-and-forget DRAM output + xi prefetch (hidden under next step)
            out[(size_t)t * BATCH * DH + oA] = vA;
            out[(size_t)t * BATCH * DH + oB] = vB;
            xiA = out[(size_t)(t + 1) * BATCH * DH + oA];
            xiB = out[(size_t)(t + 1) * BATCH * DH + oB];
            // no post-release barrier: each warp re-polls independently
        }
    }
}

// ---------------- launch (single stream, graph-capture-safe) ----------------
extern "C" void kernel_launch(void* const* d_in, const int* in_sizes, int n_in,
                              void* d_out, int out_size) {
    const float* x     = (const float*)d_in[0];
    const float* h0    = (const float*)d_in[1];
    const float* W_i2h = (const float*)d_in[2];
    const float* b_i2h = (const float*)d_in[3];
    const float* W_h2h = (const float*)d_in[4];
    const float* b_h2h = (const float*)d_in[5];
    float* out = (float*)d_out;

    float* h_last = nullptr;
    if ((long long)out_size >= (long long)(SEQ + 1) * BATCH * DH)
        h_last = out + (size_t)SEQ * BATCH * DH;

    dim3 g1(SEQ * BATCH / BM, DH / BN);
    i2h_gemm_kernel<<<g1, 256>>>(x, W_i2h, b_i2h, out);

    const int smem = 32 * WST * 4 + 8 * HST4 * 16;
    cudaFuncSetAttribute(rnn_scan_kernel,
                         cudaFuncAttributeMaxDynamicSharedMemorySize, smem);
    rnn_scan_kernel<<<128, 128, smem>>>(h0, W_h2h, b_h2h, out, h_last);
}

// round 16
// speedup vs baseline: 1.2412x; 1.0569x over previous
#include <cuda_runtime.h>
#include <math.h>

#define SEQ   2048
#define BATCH 64
#define DIN   512
#define DH    512

typedef unsigned long long u64;

// ---------------- f32x2 packed helpers (GEMM only) ----------------
__device__ __forceinline__ u64 dupf(float x) {
    u64 d; asm("mov.b64 %0, {%1, %1};" : "=l"(d) : "f"(x)); return d;
}
__device__ __forceinline__ void fma2(u64& acc, u64 a, u64 b) {
    asm("fma.rn.f32x2 %0, %1, %2, %0;" : "+l"(acc) : "l"(a), "l"(b));
}
__device__ __forceinline__ float2 unpack2(u64 v) {
    float lo, hi;
    asm("mov.b64 {%0, %1}, %2;" : "=f"(lo), "=f"(hi) : "l"(v));
    return make_float2(lo, hi);
}

// ---------------- release/acquire flag ops ----------------
__device__ __forceinline__ void st_release_gpu(unsigned* p, unsigned v) {
    asm volatile("st.global.release.gpu.u32 [%0], %1;" :: "l"(p), "r"(v) : "memory");
}
__device__ __forceinline__ unsigned ld_acquire_gpu(const unsigned* p) {
    unsigned v;
    asm volatile("ld.global.acquire.gpu.u32 %0, [%1];" : "=r"(v) : "l"(p) : "memory");
    return v;
}

// ---------------- XLA fast tanh: clamp 7.99881172180175781, passthrough ----------------
__device__ __forceinline__ float xla_tanh(float x) {
    const float kClamp = 7.99881172180175781f;
    float ax = fabsf(x);
    float xc = fminf(fmaxf(x, -kClamp), kClamp);
    float x2 = xc * xc;
    float p = __fmaf_rn(x2, -2.76076847742355e-16f, 2.00018790482477e-13f);
    p = __fmaf_rn(x2, p, -8.60467152213735e-11f);
    p = __fmaf_rn(x2, p, 5.12229709037114e-08f);
    p = __fmaf_rn(x2, p, 1.48572235717979e-05f);
    p = __fmaf_rn(x2, p, 6.37261928875436e-04f);
    p = __fmaf_rn(x2, p, 4.89352455891786e-03f);
    p = xc * p;
    float q = __fmaf_rn(x2, 1.19825839466702e-06f, 1.18534705686654e-04f);
    q = __fmaf_rn(x2, q, 2.26843463243900e-03f);
    q = __fmaf_rn(x2, q, 4.89352518554385e-03f);
    float r = __fdiv_rn(p, q);
    return (ax < 0.0004f) ? x : r;
}

// ---------------- global state ----------------
__device__ float g_ring[2][BATCH][DH];       // L2-hot double-buffered h
__device__ unsigned g_flag[8 * 16 * 32];     // per (bg,cg) step flags

// ---------------- Kernel 1: xi = x @ W_i2h^T + b_i2h (f32x2 packed) ----------------
#define BM 64
#define BN 64
#define BK 16

__global__ void __launch_bounds__(256) i2h_gemm_kernel(
    const float* __restrict__ A, const float* __restrict__ Bw,
    const float* __restrict__ bias, float* __restrict__ C)
{
    __shared__ float As[BK][BM + 4];
    __shared__ float Bs[BK][BN + 4];
    const int bm = blockIdx.x, bn = blockIdx.y, tid = threadIdx.x;
    const int tm = (tid / 16) * 4, tn = (tid % 16) * 4;
    const int lr = tid / 4, lk = (tid % 4) * 4;
    const float* Aptr = A + ((size_t)bm * BM + lr) * DIN + lk;
    const float* Bptr = Bw + ((size_t)bn * BN + lr) * DIN + lk;

    u64 acc2[4][2];
    #pragma unroll
    for (int i = 0; i < 4; i++) { acc2[i][0] = 0ull; acc2[i][1] = 0ull; }

    for (int k0 = 0; k0 < DIN; k0 += BK) {
        float4 av = *(const float4*)(Aptr + k0);
        float4 bv = *(const float4*)(Bptr + k0);
        As[lk + 0][lr] = av.x; As[lk + 1][lr] = av.y;
        As[lk + 2][lr] = av.z; As[lk + 3][lr] = av.w;
        Bs[lk + 0][lr] = bv.x; Bs[lk + 1][lr] = bv.y;
        Bs[lk + 2][lr] = bv.z; Bs[lk + 3][lr] = bv.w;
        __syncthreads();
        #pragma unroll
        for (int k = 0; k < BK; k++) {
            float4 a4 = *(const float4*)&As[k][tm];
            u64 b01 = *(const u64*)&Bs[k][tn];
            u64 b23 = *(const u64*)&Bs[k][tn + 2];
            float am[4] = {a4.x, a4.y, a4.z, a4.w};
            #pragma unroll
            for (int i = 0; i < 4; i++) {
                u64 ad = dupf(am[i]);
                fma2(acc2[i][0], ad, b01);
                fma2(acc2[i][1], ad, b23);
            }
        }
        __syncthreads();
    }

    const float b0 = bias[bn * BN + tn + 0];
    const float b1 = bias[bn * BN + tn + 1];
    const float b2 = bias[bn * BN + tn + 2];
    const float b3 = bias[bn * BN + tn + 3];
    #pragma unroll
    for (int i = 0; i < 4; i++) {
        float2 p0 = unpack2(acc2[i][0]);
        float2 p1 = unpack2(acc2[i][1]);
        float4 o;
        o.x = p0.x + b0;
        o.y = p0.y + b1;
        o.z = p1.x + b2;
        o.w = p1.y + b3;
        *(float4*)&C[((size_t)bm * BM + tm + i) * DH + bn * BN + tn] = o;
    }
}

// ---------------- Kernel 2: persistent scan (W-dedup warp mapping) ----------------
// 128 CTAs = bg(8 x 8 rows) x cg(16 x 32 cols). 128 threads = 4 warps.
// Warp w owns cols [8w, 8w+8) x ALL 8 rows. Lane: r = lane&7, cp = lane>>3;
// outputs = (row r, cols cA, cA+1) with cA = c0 + 8w + 2cp. Per k4:
//   W loads: 4 distinct chunks/warp (8-way broadcast) -> 1 wavefront each
//   h load: 8 distinct rows x 16B = 128B -> 1 exact wavefront
// Per output: identical ascending-k scalar chain -> (xi+dot)+b -> xla_tanh.
#define WST 516    // W row stride (floats)
#define HST4 129   // h row stride (float4): banks 4r, conflict-free

__global__ void __launch_bounds__(128, 1) rnn_scan_kernel(
    const float* __restrict__ h0, const float* __restrict__ W_h2h,
    const float* __restrict__ b_h2h, float* __restrict__ out,
    float* __restrict__ h_last)
{
    extern __shared__ float sm[];
    float* W_s = sm;                          // [32][WST]
    float4* h_s4 = (float4*)(sm + 32 * WST);  // [8][HST4]

    const int cg = blockIdx.x & 15;
    const int bg = blockIdx.x >> 4;
    const int c0 = cg * 32;
    const int b0 = bg * 8;
    const int tid = threadIdx.x;
    const int lane = tid & 31;
    const int w = tid >> 5;
    const int r  = lane & 7;
    const int cp = lane >> 3;
    const int cAl = w * 8 + 2 * cp;           // local col (even), 0..30
    const int cA = c0 + cAl;

    // stage W slice once: W_s[cc][k] = W_h2h[(c0+cc)*DH + k]
    for (int idx = tid; idx < 32 * 512; idx += 128) {
        int cc = idx >> 9, k = idx & 511;
        W_s[cc * WST + k] = W_h2h[(size_t)(c0 + cc) * DH + k];
    }
    const float biasA = b_h2h[cA];
    const float biasB = b_h2h[cA + 1];
    const float4* WA4 = (const float4*)&W_s[cAl * WST];
    const float4* WB4 = (const float4*)&W_s[(cAl + 1) * WST];
    const float4* Hr4 = h_s4 + r * HST4;

    // staging map: thread covers row srow, 8 strided float4s
    const int srow = tid >> 4;
    const int skq = tid & 15;
    float4* sdst = h_s4 + srow * HST4;

    const size_t rowoff = ((size_t)b0 + r) * DH + cA;   // + t*BATCH*DH
    unsigned* myflag = &g_flag[(bg * 16 + cg) * 32];
    unsigned* watch  = &g_flag[(bg * 16 + (lane & 15)) * 32];

    // prefetch xi(0)
    float2 xi = *(const float2*)(out + rowoff);
    __syncthreads();

    for (int t = 0; t < SEQ; t++) {
        // ---- wait for all 16 producer flags (parallel acquire + vote) ----
        if (t > 0) {
            const unsigned tgt = (unsigned)t;
            while (true) {
                unsigned v = (lane < 16) ? ld_acquire_gpu(watch) : tgt;
                if (__all_sync(0xFFFFFFFFu, v >= tgt)) break;
            }
        }

        // ---- cooperative staging of h(t-1): 8 rows x 512 ----
        const float4* src = (t == 0)
            ? (const float4*)(h0 + (size_t)(b0 + srow) * DH)
            : (const float4*)(g_ring[(t - 1) & 1][b0 + srow]);
        #pragma unroll
        for (int j = 0; j < 8; j++) {
            float4 v = (t == 0) ? src[skq + 16 * j] : __ldcg(src + skq + 16 * j);
            sdst[skq + 16 * j] = v;
        }
        __syncthreads();

        // ---- two ascending-k scalar chains (cols cA, cA+1; shared h row) ----
        float a0 = 0.f, a1 = 0.f;
        #pragma unroll 8
        for (int k4 = 0; k4 < 128; k4++) {
            float4 wa = WA4[k4];
            float4 wb = WB4[k4];
            float4 hv = Hr4[k4];
            a0 = __fmaf_rn(hv.x, wa.x, a0);
            a1 = __fmaf_rn(hv.x, wb.x, a1);
            a0 = __fmaf_rn(hv.y, wa.y, a0);
            a1 = __fmaf_rn(hv.y, wb.y, a1);
            a0 = __fmaf_rn(hv.z, wa.z, a0);
            a1 = __fmaf_rn(hv.z, wb.z, a1);
            a0 = __fmaf_rn(hv.w, wa.w, a0);
            a1 = __fmaf_rn(hv.w, wb.w, a1);
        }

        float vA = xla_tanh((xi.x + a0) + biasA);
        float vB = xla_tanh((xi.y + a1) + biasB);

        if (t == SEQ - 1) {
            *(float2*)(out + (size_t)t * BATCH * DH + rowoff) = make_float2(vA, vB);
            if (h_last) *(float2*)(h_last + rowoff) = make_float2(vA, vB);
            __syncthreads();
            if (tid == 0) *myflag = 0u;   // replay-clean (launch boundary fences)
        } else {
            // ring store (the only store the release must order)
            *(float2*)(&g_ring[t & 1][b0 + r][cA]) = make_float2(vA, vB);
            __syncthreads();
            if (tid == 0) st_release_gpu(myflag, (unsigned)(t + 1));
            // fire-and-forget DRAM output + xi prefetch in the poll shadow
            *(float2*)(out + (size_t)t * BATCH * DH + rowoff) = make_float2(vA, vB);
            xi = *(const float2*)(out + (size_t)(t + 1) * BATCH * DH + rowoff);
        }
    }
}

// ---------------- launch (single stream, graph-capture-safe) ----------------
extern "C" void kernel_launch(void* const* d_in, const int* in_sizes, int n_in,
                              void* d_out, int out_size) {
    const float* x     = (const float*)d_in[0];
    const float* h0    = (const float*)d_in[1];
    const float* W_i2h = (const float*)d_in[2];
    const float* b_i2h = (const float*)d_in[3];
    const float* W_h2h = (const float*)d_in[4];
    const float* b_h2h = (const float*)d_in[5];
    float* out = (float*)d_out;

    float* h_last = nullptr;
    if ((long long)out_size >= (long long)(SEQ + 1) * BATCH * DH)
        h_last = out + (size_t)SEQ * BATCH * DH;

    dim3 g1(SEQ * BATCH / BM, DH / BN);
    i2h_gemm_kernel<<<g1, 256>>>(x, W_i2h, b_i2h, out);

    const int smem = 32 * WST * 4 + 8 * HST4 * 16;
    cudaFuncSetAttribute(rnn_scan_kernel,
                         cudaFuncAttributeMaxDynamicSharedMemorySize, smem);
    rnn_scan_kernel<<<128, 128, smem>>>(h0, W_h2h, b_h2h, out, h_last);
}

// round 17
// speedup vs baseline: 1.2453x; 1.0033x over previous
#include <cuda_runtime.h>
#include <math.h>

#define SEQ   2048
#define BATCH 64
#define DIN   512
#define DH    512

typedef unsigned long long u64;

// ---------------- f32x2 packed helpers ----------------
__device__ __forceinline__ u64 dupf(float x) {
    u64 d; asm("mov.b64 %0, {%1, %1};" : "=l"(d) : "f"(x)); return d;
}
__device__ __forceinline__ void fma2(u64& acc, u64 a, u64 b) {
    asm("fma.rn.f32x2 %0, %1, %2, %0;" : "+l"(acc) : "l"(a), "l"(b));
}
__device__ __forceinline__ float2 unpack2(u64 v) {
    float lo, hi;
    asm("mov.b64 {%0, %1}, %2;" : "=f"(lo), "=f"(hi) : "l"(v));
    return make_float2(lo, hi);
}

// ---------------- release/acquire flag ops ----------------
__device__ __forceinline__ void st_release_gpu(unsigned* p, unsigned v) {
    asm volatile("st.global.release.gpu.u32 [%0], %1;" :: "l"(p), "r"(v) : "memory");
}
__device__ __forceinline__ unsigned ld_acquire_gpu(const unsigned* p) {
    unsigned v;
    asm volatile("ld.global.acquire.gpu.u32 %0, [%1];" : "=r"(v) : "l"(p) : "memory");
    return v;
}

// ---------------- XLA fast tanh: clamp 7.99881172180175781, passthrough ----------------
__device__ __forceinline__ float xla_tanh(float x) {
    const float kClamp = 7.99881172180175781f;
    float ax = fabsf(x);
    float xc = fminf(fmaxf(x, -kClamp), kClamp);
    float x2 = xc * xc;
    float p = __fmaf_rn(x2, -2.76076847742355e-16f, 2.00018790482477e-13f);
    p = __fmaf_rn(x2, p, -8.60467152213735e-11f);
    p = __fmaf_rn(x2, p, 5.12229709037114e-08f);
    p = __fmaf_rn(x2, p, 1.48572235717979e-05f);
    p = __fmaf_rn(x2, p, 6.37261928875436e-04f);
    p = __fmaf_rn(x2, p, 4.89352455891786e-03f);
    p = xc * p;
    float q = __fmaf_rn(x2, 1.19825839466702e-06f, 1.18534705686654e-04f);
    q = __fmaf_rn(x2, q, 2.26843463243900e-03f);
    q = __fmaf_rn(x2, q, 4.89352518554385e-03f);
    float r = __fdiv_rn(p, q);
    return (ax < 0.0004f) ? x : r;
}

// ---------------- global state ----------------
__device__ float g_ring[2][BATCH][DH];       // L2-hot double-buffered h
__device__ unsigned g_flag[8 * 16 * 32];     // per (bg,cg) step flags

// ---------------- Kernel 1: xi = x @ W_i2h^T + b_i2h ----------------
// CTA tile 128x128, 256 thr, warp tile 32x64, thread tile 8x8.
// A pre-duplicated (a,a) in smem -> inner loop = 6 LDS.128 + 32 FMA2 per k.
// Per element: single fp32 acc, ascending-k chain (f32x2 lane), one bias add.
#define GBM 128
#define GBN 128
#define GBK 16

__global__ void __launch_bounds__(256, 2) i2h_gemm_kernel(
    const float* __restrict__ A, const float* __restrict__ Bw,
    const float* __restrict__ bias, float* __restrict__ C)
{
    __shared__ u64   Asd[GBK][GBM];    // (a,a) dup pairs: 16 KB
    __shared__ float Bsf[GBK][GBN];    // natural (b0,b1) pairs: 8 KB

    const int bm = blockIdx.x, bn = blockIdx.y, tid = threadIdx.x;
    const int warp = tid >> 5, lane = tid & 31;
    const int wm = warp & 3, wn = warp >> 2;            // warp grid 4m x 2n
    const int mr = wm * 32 + (lane >> 3) * 8;           // thread rows mr..mr+7
    const int nc = wn * 64 + (lane & 7) * 8;            // thread cols nc..nc+7

    // staging map: thread loads row lrow, k-slice lk8..lk8+8 (2 float4 each)
    const int lrow = tid >> 1, lk8 = (tid & 1) * 8;
    const float4* Aptr = (const float4*)(A + ((size_t)bm * GBM + lrow) * DIN + lk8);
    const float4* Bptr = (const float4*)(Bw + ((size_t)bn * GBN + lrow) * DIN + lk8);

    u64 acc[8][4];
    #pragma unroll
    for (int i = 0; i < 8; i++)
        #pragma unroll
        for (int j = 0; j < 4; j++) acc[i][j] = 0ull;

    // prefetch k0 = 0
    float4 a0 = Aptr[0], a1 = Aptr[1];
    float4 b0 = Bptr[0], b1 = Bptr[1];

    for (int k0 = 0; k0 < DIN; k0 += GBK) {
        __syncthreads();
        Asd[lk8 + 0][lrow] = dupf(a0.x);
        Asd[lk8 + 1][lrow] = dupf(a0.y);
        Asd[lk8 + 2][lrow] = dupf(a0.z);
        Asd[lk8 + 3][lrow] = dupf(a0.w);
        Asd[lk8 + 4][lrow] = dupf(a1.x);
        Asd[lk8 + 5][lrow] = dupf(a1.y);
        Asd[lk8 + 6][lrow] = dupf(a1.z);
        Asd[lk8 + 7][lrow] = dupf(a1.w);
        Bsf[lk8 + 0][lrow] = b0.x;
        Bsf[lk8 + 1][lrow] = b0.y;
        Bsf[lk8 + 2][lrow] = b0.z;
        Bsf[lk8 + 3][lrow] = b0.w;
        Bsf[lk8 + 4][lrow] = b1.x;
        Bsf[lk8 + 5][lrow] = b1.y;
        Bsf[lk8 + 6][lrow] = b1.z;
        Bsf[lk8 + 7][lrow] = b1.w;
        __syncthreads();

        // prefetch next k0 tile (latency hidden under the inner loop)
        if (k0 + GBK < DIN) {
            const float4* An = (const float4*)((const float*)Aptr + k0 + GBK);
            const float4* Bn = (const float4*)((const float*)Bptr + k0 + GBK);
            a0 = An[0]; a1 = An[1];
            b0 = Bn[0]; b1 = Bn[1];
        }

        #pragma unroll
        for (int k = 0; k < GBK; k++) {
            u64 af[8];
            #pragma unroll
            for (int i = 0; i < 8; i += 2)
                *(ulonglong2*)&af[i] = *(const ulonglong2*)&Asd[k][mr + i];
            u64 bf[4];
            *(ulonglong2*)&bf[0] = *(const ulonglong2*)&Bsf[k][nc];
            *(ulonglong2*)&bf[2] = *(const ulonglong2*)&Bsf[k][nc + 4];
            #pragma unroll
            for (int i = 0; i < 8; i++)
                #pragma unroll
                for (int j = 0; j < 4; j++)
                    fma2(acc[i][j], af[i], bf[j]);
        }
    }

    float bs[8];
    #pragma unroll
    for (int j = 0; j < 8; j++) bs[j] = bias[bn * GBN + nc + j];
    #pragma unroll
    for (int i = 0; i < 8; i++) {
        float2 p0 = unpack2(acc[i][0]);
        float2 p1 = unpack2(acc[i][1]);
        float2 p2 = unpack2(acc[i][2]);
        float2 p3 = unpack2(acc[i][3]);
        float4 olo, ohi;
        olo.x = p0.x + bs[0]; olo.y = p0.y + bs[1];
        olo.z = p1.x + bs[2]; olo.w = p1.y + bs[3];
        ohi.x = p2.x + bs[4]; ohi.y = p2.y + bs[5];
        ohi.z = p3.x + bs[6]; ohi.w = p3.y + bs[7];
        float* crow = C + ((size_t)bm * GBM + mr + i) * DH + bn * GBN + nc;
        *(float4*)crow = olo;
        *(float4*)(crow + 4) = ohi;
    }
}

// ---------------- Kernel 2: persistent scan (R16 champion, unchanged) ----------------
#define WST 516    // W row stride (floats)
#define HST4 129   // h row stride (float4): banks 4r, conflict-free

__global__ void __launch_bounds__(128, 1) rnn_scan_kernel(
    const float* __restrict__ h0, const float* __restrict__ W_h2h,
    const float* __restrict__ b_h2h, float* __restrict__ out,
    float* __restrict__ h_last)
{
    extern __shared__ float sm[];
    float* W_s = sm;                          // [32][WST]
    float4* h_s4 = (float4*)(sm + 32 * WST);  // [8][HST4]

    const int cg = blockIdx.x & 15;
    const int bg = blockIdx.x >> 4;
    const int c0 = cg * 32;
    const int b0 = bg * 8;
    const int tid = threadIdx.x;
    const int lane = tid & 31;
    const int w = tid >> 5;
    const int r  = lane & 7;
    const int cp = lane >> 3;
    const int cAl = w * 8 + 2 * cp;           // local col (even), 0..30
    const int cA = c0 + cAl;

    for (int idx = tid; idx < 32 * 512; idx += 128) {
        int cc = idx >> 9, k = idx & 511;
        W_s[cc * WST + k] = W_h2h[(size_t)(c0 + cc) * DH + k];
    }
    const float biasA = b_h2h[cA];
    const float biasB = b_h2h[cA + 1];
    const float4* WA4 = (const float4*)&W_s[cAl * WST];
    const float4* WB4 = (const float4*)&W_s[(cAl + 1) * WST];
    const float4* Hr4 = h_s4 + r * HST4;

    const int srow = tid >> 4;
    const int skq = tid & 15;
    float4* sdst = h_s4 + srow * HST4;

    const size_t rowoff = ((size_t)b0 + r) * DH + cA;   // + t*BATCH*DH
    unsigned* myflag = &g_flag[(bg * 16 + cg) * 32];
    unsigned* watch  = &g_flag[(bg * 16 + (lane & 15)) * 32];

    float2 xi = *(const float2*)(out + rowoff);
    __syncthreads();

    for (int t = 0; t < SEQ; t++) {
        if (t > 0) {
            const unsigned tgt = (unsigned)t;
            while (true) {
                unsigned v = (lane < 16) ? ld_acquire_gpu(watch) : tgt;
                if (__all_sync(0xFFFFFFFFu, v >= tgt)) break;
            }
        }

        const float4* src = (t == 0)
            ? (const float4*)(h0 + (size_t)(b0 + srow) * DH)
            : (const float4*)(g_ring[(t - 1) & 1][b0 + srow]);
        #pragma unroll
        for (int j = 0; j < 8; j++) {
            float4 v = (t == 0) ? src[skq + 16 * j] : __ldcg(src + skq + 16 * j);
            sdst[skq + 16 * j] = v;
        }
        __syncthreads();

        float a0 = 0.f, a1 = 0.f;
        #pragma unroll 8
        for (int k4 = 0; k4 < 128; k4++) {
            float4 wa = WA4[k4];
            float4 wb = WB4[k4];
            float4 hv = Hr4[k4];
            a0 = __fmaf_rn(hv.x, wa.x, a0);
            a1 = __fmaf_rn(hv.x, wb.x, a1);
            a0 = __fmaf_rn(hv.y, wa.y, a0);
            a1 = __fmaf_rn(hv.y, wb.y, a1);
            a0 = __fmaf_rn(hv.z, wa.z, a0);
            a1 = __fmaf_rn(hv.z, wb.z, a1);
            a0 = __fmaf_rn(hv.w, wa.w, a0);
            a1 = __fmaf_rn(hv.w, wb.w, a1);
        }

        float vA = xla_tanh((xi.x + a0) + biasA);
        float vB = xla_tanh((xi.y + a1) + biasB);

        if (t == SEQ - 1) {
            *(float2*)(out + (size_t)t * BATCH * DH + rowoff) = make_float2(vA, vB);
            if (h_last) *(float2*)(h_last + rowoff) = make_float2(vA, vB);
            __syncthreads();
            if (tid == 0) *myflag = 0u;   // replay-clean (launch boundary fences)
        } else {
            *(float2*)(&g_ring[t & 1][b0 + r][cA]) = make_float2(vA, vB);
            __syncthreads();
            if (tid == 0) st_release_gpu(myflag, (unsigned)(t + 1));
            *(float2*)(out + (size_t)t * BATCH * DH + rowoff) = make_float2(vA, vB);
            xi = *(const float2*)(out + (size_t)(t + 1) * BATCH * DH + rowoff);
        }
    }
}

// ---------------- launch (single stream, graph-capture-safe) ----------------
extern "C" void kernel_launch(void* const* d_in, const int* in_sizes, int n_in,
                              void* d_out, int out_size) {
    const float* x     = (const float*)d_in[0];
    const float* h0    = (const float*)d_in[1];
    const float* W_i2h = (const float*)d_in[2];
    const float* b_i2h = (const float*)d_in[3];
    const float* W_h2h = (const float*)d_in[4];
    const float* b_h2h = (const float*)d_in[5];
    float* out = (float*)d_out;

    float* h_last = nullptr;
    if ((long long)out_size >= (long long)(SEQ + 1) * BATCH * DH)
        h_last = out + (size_t)SEQ * BATCH * DH;

    dim3 g1(SEQ * BATCH / GBM, DH / GBN);   // (1024, 4)
    i2h_gemm_kernel<<<g1, 256>>>(x, W_i2h, b_i2h, out);

    const int smem = 32 * WST * 4 + 8 * HST4 * 16;
    cudaFuncSetAttribute(rnn_scan_kernel,
                         cudaFuncAttributeMaxDynamicSharedMemorySize, smem);
    rnn_scan_kernel<<<128, 128, smem>>>(h0, W_h2h, b_h2h, out, h_last);
}